// round 11
// baseline (speedup 1.0000x reference)
#include <cuda_runtime.h>
#include <math.h>

// Problem shape (fixed by the reference)
#define NB     16
#define NS     8192
#define NKV    512
#define NE     512
#define NH     8
#define ND     64
#define NCHUNK 8
#define CHUNK  1024
#define TILE   32
#define NTILES (CHUNK/TILE)   // 32
#define TB     512

// Scratch (device globals; allocations forbidden)
__device__ __align__(16) float g_q[NB*NE];
__device__ __align__(16) float g_P[NB*NH*NKV];
__device__ __align__(16) float g_partC[(size_t)NB*NCHUNK*NH*NKV];
__device__ __align__(16) float g_partZ[NB*NCHUNK*NH];
__device__ __align__(16) float g_cbar[NB*NH*NKV];
__device__ __align__(16) float g_ctx[NB*NE];

// ---- packed f32x2 helpers ----
typedef unsigned long long u64;
__device__ __forceinline__ u64 ffma2(u64 a, u64 b, u64 c) {
    u64 d;
    asm("fma.rn.f32x2 %0, %1, %2, %3;" : "=l"(d) : "l"(a), "l"(b), "l"(c));
    return d;
}
__device__ __forceinline__ float lo2(u64 v){ return __uint_as_float((unsigned)v); }
__device__ __forceinline__ float hi2(u64 v){ return __uint_as_float((unsigned)(v>>32)); }
__device__ __forceinline__ u64 dup2(float v){
    u64 r; asm("mov.b64 %0, {%1, %1};" : "=l"(r) : "f"(v)); return r;
}
__device__ __forceinline__ void cpa16(unsigned dst, const void* src){
    asm volatile("cp.async.cg.shared.global [%0], [%1], 16;" :: "r"(dst), "l"(src));
}

// ---------------------------------------------------------------------------
// A1: q[b,e] = query[b,:] @ Wq[:,e] + bq[e].
// grid (16 b, 8 eblocks of 64) x 256 = 64 cols x 4-way split-K, MLP8.
// ---------------------------------------------------------------------------
__global__ void __launch_bounds__(256) kernA1(
    const float* __restrict__ query, const float* __restrict__ Wq,
    const float* __restrict__ bq)
{
    __shared__ float qs[NKV];
    __shared__ float red[256];
    const int b = blockIdx.x, eb = blockIdx.y, t = threadIdx.x;
    for (int i = t; i < NKV; i += 256) qs[i] = query[b*NKV + i];
    __syncthreads();
    const int e = eb*64 + (t & 63), kp = t >> 6;
    const float* q  = qs + kp*128;
    const float* wq = Wq + (size_t)(kp*128)*NE + e;
    float s0=0,s1=0,s2=0,s3=0,s4=0,s5=0,s6=0,s7=0;
    #pragma unroll 4
    for (int j = 0; j < 128; j += 8) {
        s0 = fmaf(q[j+0], wq[(size_t)(j+0)*NE], s0);
        s1 = fmaf(q[j+1], wq[(size_t)(j+1)*NE], s1);
        s2 = fmaf(q[j+2], wq[(size_t)(j+2)*NE], s2);
        s3 = fmaf(q[j+3], wq[(size_t)(j+3)*NE], s3);
        s4 = fmaf(q[j+4], wq[(size_t)(j+4)*NE], s4);
        s5 = fmaf(q[j+5], wq[(size_t)(j+5)*NE], s5);
        s6 = fmaf(q[j+6], wq[(size_t)(j+6)*NE], s6);
        s7 = fmaf(q[j+7], wq[(size_t)(j+7)*NE], s7);
    }
    red[t] = ((s0+s1)+(s2+s3))+((s4+s5)+(s6+s7));
    __syncthreads();
    if (t < 64)
        g_q[b*NE + e] = ((red[t]+red[t+64])+(red[t+128]+red[t+192])) + bq[e];
}

// ---------------------------------------------------------------------------
// A2: P[b,h,j] = 0.125 * sum_d g_q[b,h*64+d] * Wk[j,h*64+d]
// ---------------------------------------------------------------------------
__global__ void __launch_bounds__(256) kernA2(const float* __restrict__ Wk)
{
    __shared__ float wks[64*65];
    __shared__ float qhs[16*64];
    const int jb = blockIdx.x, h = blockIdx.y, t = threadIdx.x;

    for (int i = t; i < 64*16; i += 256) {
        int j = i >> 4, d4 = i & 15;
        float4 v = *(const float4*)(Wk + (size_t)(jb*64 + j)*NE + h*ND + d4*4);
        wks[j*65 + d4*4+0] = v.x; wks[j*65 + d4*4+1] = v.y;
        wks[j*65 + d4*4+2] = v.z; wks[j*65 + d4*4+3] = v.w;
    }
    for (int i = t; i < 16*64; i += 256) {
        int bb = i >> 6, d = i & 63;
        qhs[bb*64 + d] = g_q[bb*NE + h*ND + d];
    }
    __syncthreads();

    const int j = t & 63, bg = t >> 6;
    float acc[4] = {0.f,0.f,0.f,0.f};
    const float* wr = wks + j*65;
    #pragma unroll
    for (int d = 0; d < 64; ++d) {
        float wv = wr[d];
        #pragma unroll
        for (int bb = 0; bb < 4; ++bb)
            acc[bb] = fmaf(wv, qhs[(bg*4 + bb)*64 + d], acc[bb]);
    }
    #pragma unroll
    for (int bb = 0; bb < 4; ++bb)
        g_P[((size_t)(bg*4 + bb)*NH + h)*NKV + jb*64 + j] = acc[bb]*0.125f;
}

// ---------------------------------------------------------------------------
// B: fused pass over kv. 512 threads / 16 warps (4 per SMSP, <=128 regs).
// Two phases per 32-row tile with DIFFERENT warp mappings:
//  logit phase: warp w -> rows (w>>1)*4..+3, heads (w&1)*4..+3 (P in regs);
//    per 2-row subgroup: dot, fold16/8, 3-stage reduce-scatter over 8, exp;
//    weights stored to smem as pre-duplicated (w,w) u64 pairs.
//  accum phase: warp w -> heads (w&1)*4..+3, cols (w>>1)*64..+63;
//    per lane acc = 4 heads x 1 col-pair (8 regs); kv via LDS.64,
//    w via broadcast LDS.128. Each (h,col) owned by ONE warp ->
//    epilogue writes g_partC directly (no cross-warp reduce).
// No-max softmax (|logit| < ~3). Triple-buffered cp.async ring.
// ---------------------------------------------------------------------------
__global__ void __launch_bounds__(TB, 1) kernB(const float* __restrict__ kv)
{
    extern __shared__ float sh[];
    float* kvs = sh;                           // [3][TILE][NKV]
    u64*   wsm = (u64*)(sh + 3*TILE*NKV);      // [2][TILE][NH] (w,w) pairs
    float* zs  = (float*)(wsm + 2*TILE*NH);    // [16][8]

    const int tid  = threadIdx.x;
    const int wid  = tid >> 5, lane = tid & 31;
    const int rb = wid >> 1, hg = wid & 1;     // logit mapping
    const int cb = wid >> 1;                   // accum mapping (cols cb*64..)
    const int chunk = blockIdx.x, b = blockIdx.y;

    // P slice in registers: 4 heads x 4 chunks x 4 floats (per lane)
    u64 Pr[4][4][2];
    #pragma unroll
    for (int h = 0; h < 4; ++h)
        #pragma unroll
        for (int c = 0; c < 4; ++c) {
            const float* p = g_P + ((size_t)b*NH + hg*4 + h)*NKV + c*128 + lane*4;
            ulonglong2 v = *(const ulonglong2*)p;
            Pr[h][c][0] = v.x; Pr[h][c][1] = v.y;
        }

    u64 acc[4];                                // 4 heads x (2 packed cols)
    #pragma unroll
    for (int h = 0; h < 4; ++h) acc[h] = 0ull;
    float zacc = 0.f;

    const unsigned kvs_u = (unsigned)__cvta_generic_to_shared(kvs);
    const float4* src_base = (const float4*)kv
        + ((size_t)b*NS + (size_t)chunk*CHUNK)*(NKV/4);

    // prologue: stage tiles 0 and 1
    #pragma unroll
    for (int pt = 0; pt < 2; ++pt) {
        const float4* s = src_base + (size_t)pt*TILE*(NKV/4);
        unsigned dst = kvs_u + (unsigned)(pt*TILE*NKV*4);
        #pragma unroll
        for (int k = 0; k < (TILE*NKV/4)/TB; ++k) {
            int i = tid + k*TB;
            cpa16(dst + (unsigned)i*16u, s + i);
        }
        asm volatile("cp.async.commit_group;");
    }

    for (int t = 0; t < NTILES; ++t) {
        if (t < NTILES-1) asm volatile("cp.async.wait_group 1;");
        else              asm volatile("cp.async.wait_group 0;");
        __syncthreads();

        if (t + 2 < NTILES) {   // stage t+2 into buffer (t+2)%3
            const float4* s = src_base + (size_t)(t+2)*TILE*(NKV/4);
            unsigned dst = kvs_u + (unsigned)(((t+2)%3)*TILE*NKV*4);
            #pragma unroll
            for (int k = 0; k < (TILE*NKV/4)/TB; ++k) {
                int i = tid + k*TB;
                cpa16(dst + (unsigned)i*16u, s + i);
            }
            asm volatile("cp.async.commit_group;");
        }

        // ---- logit phase: rows rb*4..+3, heads hg*4..+3 ----
        {
            const float* kbw = kvs + (t%3)*TILE*NKV + rb*4*NKV;
            u64* wrow = wsm + (t & 1)*TILE*NH;
            #pragma unroll
            for (int sub = 0; sub < 2; ++sub) {
                u64 la[2][4];
                #pragma unroll
                for (int r = 0; r < 2; ++r)
                    #pragma unroll
                    for (int h = 0; h < 4; ++h) la[r][h] = 0ull;
                #pragma unroll
                for (int c = 0; c < 4; ++c) {
                    ulonglong2 x0 = *(const ulonglong2*)(kbw + (sub*2+0)*NKV + c*128 + lane*4);
                    ulonglong2 x1 = *(const ulonglong2*)(kbw + (sub*2+1)*NKV + c*128 + lane*4);
                    #pragma unroll
                    for (int h = 0; h < 4; ++h) {
                        la[0][h] = ffma2(x0.x, Pr[h][c][0], la[0][h]);
                        la[0][h] = ffma2(x0.y, Pr[h][c][1], la[0][h]);
                        la[1][h] = ffma2(x1.x, Pr[h][c][0], la[1][h]);
                        la[1][h] = ffma2(x1.y, Pr[h][c][1], la[1][h]);
                    }
                }
                float v[8];
                #pragma unroll
                for (int r = 0; r < 2; ++r)
                    #pragma unroll
                    for (int h = 0; h < 4; ++h)
                        v[r*4+h] = lo2(la[r][h]) + hi2(la[r][h]);
                // fold lane bits 4 and 3, then reduce-scatter over 8:
                // lane l (l<8) ends with full logit of idx l = r*4+h
                #pragma unroll
                for (int j = 0; j < 8; ++j) v[j] += __shfl_xor_sync(0xffffffffu, v[j], 16);
                #pragma unroll
                for (int j = 0; j < 8; ++j) v[j] += __shfl_xor_sync(0xffffffffu, v[j], 8);
                #pragma unroll
                for (int half = 4; half >= 1; half >>= 1) {
                    const bool up = (lane & half) != 0;
                    #pragma unroll
                    for (int j = 0; j < half; ++j) {
                        float mine   = up ? v[j+half] : v[j];
                        float theirs = up ? v[j]      : v[j+half];
                        v[j] = mine + __shfl_xor_sync(0xffffffffu, theirs, half);
                    }
                }
                if (lane < 8) {
                    float w = __expf(v[0]);   // idx = lane: r=(lane>>2), h=lane&3
                    zacc += w;
                    const int row  = rb*4 + sub*2 + (lane >> 2);
                    const int head = hg*4 + (lane & 3);
                    wrow[row*NH + head] = dup2(w);
                }
            }
        }
        __syncthreads();

        // ---- accum phase: heads hg*4..+3, cols cb*64 + lane*2 (+1) ----
        {
            const float* kbc = kvs + (t%3)*TILE*NKV + cb*64 + lane*2;
            const u64*   wb  = wsm + (t & 1)*TILE*NH + hg*4;
            #pragma unroll 8
            for (int r = 0; r < TILE; ++r) {
                u64 xp = *(const u64*)(kbc + r*NKV);
                ulonglong2 wA = *(const ulonglong2*)(wb + r*NH);      // heads 0,1
                ulonglong2 wB = *(const ulonglong2*)(wb + r*NH + 2);  // heads 2,3
                acc[0] = ffma2(wA.x, xp, acc[0]);
                acc[1] = ffma2(wA.y, xp, acc[1]);
                acc[2] = ffma2(wB.x, xp, acc[2]);
                acc[3] = ffma2(wB.y, xp, acc[3]);
            }
        }
    }

    // ---- epilogue: direct writes (no cross-warp reduce needed) ----
    if (lane < 8) zs[wid*8 + lane] = zacc;
    __syncthreads();

    const int part = b*NCHUNK + chunk;
    {
        float* pc = g_partC + (size_t)part*NH*NKV;
        #pragma unroll
        for (int h = 0; h < 4; ++h)
            *(u64*)(pc + (size_t)(hg*4 + h)*NKV + cb*64 + lane*2) = acc[h];
    }
    if (tid < NH) {
        const int hg2 = tid >> 2, hl = tid & 3;
        float Z = 0.f;
        #pragma unroll
        for (int rb2 = 0; rb2 < 8; ++rb2) {
            const int w = rb2*2 + hg2;
            Z += zs[w*8 + hl] + zs[w*8 + 4 + hl];
        }
        g_partZ[part*NH + tid] = Z;
    }
}

// ---------------------------------------------------------------------------
// C1: cbar[b,h,j] = (sum_i partC[b,i,h,j]) / Z[b,h].  grid 64 x 256
// ---------------------------------------------------------------------------
__global__ void __launch_bounds__(256) kernC1()
{
    const int idx = blockIdx.x*256 + threadIdx.x;      // 16384 float4 slots
    const int b = idx >> 10, rem = idx & 1023, h = rem >> 7, j4 = rem & 127;
    float Z = 0.f;
    #pragma unroll
    for (int i = 0; i < NCHUNK; ++i) Z += g_partZ[(b*NCHUNK + i)*NH + h];
    const float invZ = 1.0f / Z;
    float4 s = make_float4(0.f,0.f,0.f,0.f);
    #pragma unroll
    for (int i = 0; i < NCHUNK; ++i) {
        const float4* p = (const float4*)(g_partC + (((size_t)(b*NCHUNK + i)*NH + h) << 9));
        float4 v = p[j4];
        s.x += v.x; s.y += v.y; s.z += v.z; s.w += v.w;
    }
    s.x *= invZ; s.y *= invZ; s.z *= invZ; s.w *= invZ;
    ((float4*)g_cbar)[((size_t)(b*NH + h) << 7) + j4] = s;
}

// ---------------------------------------------------------------------------
// C2: ctx[b, h*64+col] = cbar[b,h,:] @ Wv[:, h*64+col] + bv.
// grid (16 b, 8 h) x 256 = 64 cols x 4-way split-K, MLP8.
// ---------------------------------------------------------------------------
__global__ void __launch_bounds__(256) kernC2(
    const float* __restrict__ Wv, const float* __restrict__ bv)
{
    __shared__ float cb_s[NKV];
    __shared__ float red[256];
    const int b = blockIdx.x, h = blockIdx.y, t = threadIdx.x;
    for (int i = t; i < NKV; i += 256) cb_s[i] = g_cbar[(size_t)(b*NH + h)*NKV + i];
    __syncthreads();
    const int col = h*64 + (t & 63), kp = t >> 6;
    const float* c  = cb_s + kp*128;
    const float* wv = Wv + (size_t)(kp*128)*NE + col;
    float s0=0,s1=0,s2=0,s3=0,s4=0,s5=0,s6=0,s7=0;
    #pragma unroll 4
    for (int j = 0; j < 128; j += 8) {
        s0 = fmaf(c[j+0], wv[(size_t)(j+0)*NE], s0);
        s1 = fmaf(c[j+1], wv[(size_t)(j+1)*NE], s1);
        s2 = fmaf(c[j+2], wv[(size_t)(j+2)*NE], s2);
        s3 = fmaf(c[j+3], wv[(size_t)(j+3)*NE], s3);
        s4 = fmaf(c[j+4], wv[(size_t)(j+4)*NE], s4);
        s5 = fmaf(c[j+5], wv[(size_t)(j+5)*NE], s5);
        s6 = fmaf(c[j+6], wv[(size_t)(j+6)*NE], s6);
        s7 = fmaf(c[j+7], wv[(size_t)(j+7)*NE], s7);
    }
    red[t] = ((s0+s1)+(s2+s3))+((s4+s5)+(s6+s7));
    __syncthreads();
    if (t < 64)
        g_ctx[b*NE + col] = ((red[t]+red[t+64])+(red[t+128]+red[t+192])) + bv[col];
}

// ---------------------------------------------------------------------------
// D: out[b] = ctx[b] @ Wo + bo.  grid (16 b, 8 colblocks) x 256, MLP8.
// ---------------------------------------------------------------------------
__global__ void __launch_bounds__(256) kernD(
    const float* __restrict__ Wo, const float* __restrict__ bo,
    float* __restrict__ out)
{
    __shared__ float cs[NE];
    __shared__ float red[256];
    const int b = blockIdx.x, cb = blockIdx.y, t = threadIdx.x;
    for (int i = t; i < NE; i += 256) cs[i] = g_ctx[b*NE + i];
    __syncthreads();
    const int col = cb*64 + (t & 63), kp = t >> 6;
    const float* c  = cs + kp*128;
    const float* wo = Wo + (size_t)(kp*128)*NE + col;
    float s0=0,s1=0,s2=0,s3=0,s4=0,s5=0,s6=0,s7=0;
    #pragma unroll 4
    for (int j = 0; j < 128; j += 8) {
        s0 = fmaf(c[j+0], wo[(size_t)(j+0)*NE], s0);
        s1 = fmaf(c[j+1], wo[(size_t)(j+1)*NE], s1);
        s2 = fmaf(c[j+2], wo[(size_t)(j+2)*NE], s2);
        s3 = fmaf(c[j+3], wo[(size_t)(j+3)*NE], s3);
        s4 = fmaf(c[j+4], wo[(size_t)(j+4)*NE], s4);
        s5 = fmaf(c[j+5], wo[(size_t)(j+5)*NE], s5);
        s6 = fmaf(c[j+6], wo[(size_t)(j+6)*NE], s6);
        s7 = fmaf(c[j+7], wo[(size_t)(j+7)*NE], s7);
    }
    red[t] = ((s0+s1)+(s2+s3))+((s4+s5)+(s6+s7));
    __syncthreads();
    if (t < 64)
        out[b*NE + col] = ((red[t]+red[t+64])+(red[t+128]+red[t+192])) + bo[col];
}

// ---------------------------------------------------------------------------
extern "C" void kernel_launch(void* const* d_in, const int* in_sizes, int n_in,
                              void* d_out, int out_size)
{
    (void)in_sizes; (void)n_in; (void)out_size;
    const float* query = (const float*)d_in[0];
    const float* kv    = (const float*)d_in[1];
    const float* Wq    = (const float*)d_in[2];
    const float* bq    = (const float*)d_in[3];
    const float* Wk    = (const float*)d_in[4];
    // d_in[5] = bk: softmax-invariant, unused
    const float* Wv    = (const float*)d_in[6];
    const float* bv    = (const float*)d_in[7];
    const float* Wo    = (const float*)d_in[8];
    const float* bo    = (const float*)d_in[9];
    float* out = (float*)d_out;

    const size_t shmB = (size_t)(3*TILE*NKV)*sizeof(float)
                      + (size_t)(2*TILE*NH)*sizeof(u64) + 16*8*sizeof(float);
    cudaFuncSetAttribute(kernB, cudaFuncAttributeMaxDynamicSharedMemorySize, (int)shmB);

    kernA1<<<dim3(NB, 8), 256>>>(query, Wq, bq);
    kernA2<<<dim3(8, NH), 256>>>(Wk);
    kernB <<<dim3(NCHUNK, NB), TB, shmB>>>(kv);
    kernC1<<<64, 256>>>();
    kernC2<<<dim3(NB, NH), 256>>>(Wv, bv);
    kernD <<<dim3(NB, 8), 256>>>(Wo, bo, out);
}

// round 12
// speedup vs baseline: 1.2195x; 1.2195x over previous
#include <cuda_runtime.h>
#include <math.h>

// Problem shape (fixed by the reference)
#define NB     16
#define NS     8192
#define NKV    512
#define NE     512
#define NH     8
#define ND     64
#define NCHUNK 8
#define CHUNK  1024
#define TILE   32
#define NTILES (CHUNK/TILE)   // 32
#define TB     256

// Scratch (device globals; allocations forbidden)
__device__ __align__(16) float g_q[NB*NE];
__device__ __align__(16) float g_P[NB*NH*NKV];
__device__ __align__(16) float g_partC[(size_t)NB*NCHUNK*NH*NKV];
__device__ __align__(16) float g_partZ[NB*NCHUNK*NH];
__device__ __align__(16) float g_ctx[NB*NE];

// ---- packed f32x2 helpers ----
typedef unsigned long long u64;
__device__ __forceinline__ u64 ffma2(u64 a, u64 b, u64 c) {
    u64 d;
    asm("fma.rn.f32x2 %0, %1, %2, %3;" : "=l"(d) : "l"(a), "l"(b), "l"(c));
    return d;
}
__device__ __forceinline__ float lo2(u64 v){ return __uint_as_float((unsigned)v); }
__device__ __forceinline__ float hi2(u64 v){ return __uint_as_float((unsigned)(v>>32)); }
__device__ __forceinline__ u64 dup2(float v){
    u64 r; asm("mov.b64 %0, {%1, %1};" : "=l"(r) : "f"(v)); return r;
}
__device__ __forceinline__ void cpa16(unsigned dst, const void* src){
    asm volatile("cp.async.cg.shared.global [%0], [%1], 16;" :: "r"(dst), "l"(src));
}

// ---------------------------------------------------------------------------
// A1: q[b,e] = query[b,:] @ Wq[:,e] + bq[e].
// grid (16 b, 8 eblocks of 64) x 256 = 64 cols x 4-way split-K, MLP8.
// ---------------------------------------------------------------------------
__global__ void __launch_bounds__(256) kernA1(
    const float* __restrict__ query, const float* __restrict__ Wq,
    const float* __restrict__ bq)
{
    __shared__ float qs[NKV];
    __shared__ float red[256];
    const int b = blockIdx.x, eb = blockIdx.y, t = threadIdx.x;
    for (int i = t; i < NKV; i += 256) qs[i] = query[b*NKV + i];
    __syncthreads();
    const int e = eb*64 + (t & 63), kp = t >> 6;
    const float* q  = qs + kp*128;
    const float* wq = Wq + (size_t)(kp*128)*NE + e;
    float s0=0,s1=0,s2=0,s3=0,s4=0,s5=0,s6=0,s7=0;
    #pragma unroll 4
    for (int j = 0; j < 128; j += 8) {
        s0 = fmaf(q[j+0], wq[(size_t)(j+0)*NE], s0);
        s1 = fmaf(q[j+1], wq[(size_t)(j+1)*NE], s1);
        s2 = fmaf(q[j+2], wq[(size_t)(j+2)*NE], s2);
        s3 = fmaf(q[j+3], wq[(size_t)(j+3)*NE], s3);
        s4 = fmaf(q[j+4], wq[(size_t)(j+4)*NE], s4);
        s5 = fmaf(q[j+5], wq[(size_t)(j+5)*NE], s5);
        s6 = fmaf(q[j+6], wq[(size_t)(j+6)*NE], s6);
        s7 = fmaf(q[j+7], wq[(size_t)(j+7)*NE], s7);
    }
    red[t] = ((s0+s1)+(s2+s3))+((s4+s5)+(s6+s7));
    __syncthreads();
    if (t < 64)
        g_q[b*NE + e] = ((red[t]+red[t+64])+(red[t+128]+red[t+192])) + bq[e];
}

// ---------------------------------------------------------------------------
// A2: P[b,h,j] = 0.125 * sum_d g_q[b,h*64+d] * Wk[j,h*64+d]
// ---------------------------------------------------------------------------
__global__ void __launch_bounds__(256) kernA2(const float* __restrict__ Wk)
{
    __shared__ float wks[64*65];
    __shared__ float qhs[16*64];
    const int jb = blockIdx.x, h = blockIdx.y, t = threadIdx.x;

    for (int i = t; i < 64*16; i += 256) {
        int j = i >> 4, d4 = i & 15;
        float4 v = *(const float4*)(Wk + (size_t)(jb*64 + j)*NE + h*ND + d4*4);
        wks[j*65 + d4*4+0] = v.x; wks[j*65 + d4*4+1] = v.y;
        wks[j*65 + d4*4+2] = v.z; wks[j*65 + d4*4+3] = v.w;
    }
    for (int i = t; i < 16*64; i += 256) {
        int bb = i >> 6, d = i & 63;
        qhs[bb*64 + d] = g_q[bb*NE + h*ND + d];
    }
    __syncthreads();

    const int j = t & 63, bg = t >> 6;
    float acc[4] = {0.f,0.f,0.f,0.f};
    const float* wr = wks + j*65;
    #pragma unroll
    for (int d = 0; d < 64; ++d) {
        float wv = wr[d];
        #pragma unroll
        for (int bb = 0; bb < 4; ++bb)
            acc[bb] = fmaf(wv, qhs[(bg*4 + bb)*64 + d], acc[bb]);
    }
    #pragma unroll
    for (int bb = 0; bb < 4; ++bb)
        g_P[((size_t)(bg*4 + bb)*NH + h)*NKV + jb*64 + j] = acc[bb]*0.125f;
}

// ---------------------------------------------------------------------------
// B: fused single-phase pass over kv. 256 threads / 8 warps (2 per SMSP).
// warp w: rows rb*8..+7 (rb=w>>1), heads hg*4..+3 (hg=w&1).
// Rows processed in TWO 4-row groups; P read from SMEM (no Pr registers ->
// no spills even with 4-row groups). Per group: kv rows in registers feed
// both the logit dot (fold16 + 4-stage reduce-scatter over 16, ONE exp) and
// the weighted accumulation into a 4-head x 16-col register tile.
// No-max softmax (|logit| < ~3). Triple-buffered cp.async ring.
// ---------------------------------------------------------------------------
__global__ void __launch_bounds__(TB, 1) kernB(const float* __restrict__ kv)
{
    extern __shared__ float sh[];
    float* kvs = sh;                 // [3][TILE][NKV] (reused as reduce buffer)
    float* Ps  = sh + 3*TILE*NKV;    // [NH][NKV]
    float* zs  = Ps + NH*NKV;        // [128]

    const int tid  = threadIdx.x;
    const int wid  = tid >> 5, lane = tid & 31;
    const int rb = wid >> 1, hg = wid & 1;
    const int chunk = blockIdx.x, b = blockIdx.y;

    // stage P into smem once (16 KB)
    {
        const float4* Pg = (const float4*)(g_P + (size_t)b*NH*NKV);
        for (int i = tid; i < NH*NKV/4; i += TB) ((float4*)Ps)[i] = Pg[i];
    }

    u64 acc[4][4][2];
    #pragma unroll
    for (int h = 0; h < 4; ++h)
        #pragma unroll
        for (int c = 0; c < 4; ++c) { acc[h][c][0] = 0ull; acc[h][c][1] = 0ull; }
    float zacc = 0.f;

    const unsigned kvs_u = (unsigned)__cvta_generic_to_shared(kvs);
    const float4* src_base = (const float4*)kv
        + ((size_t)b*NS + (size_t)chunk*CHUNK)*(NKV/4);

    // prologue: stage tiles 0 and 1
    #pragma unroll
    for (int pt = 0; pt < 2; ++pt) {
        const float4* s = src_base + (size_t)pt*TILE*(NKV/4);
        unsigned dst = kvs_u + (unsigned)(pt*TILE*NKV*4);
        #pragma unroll
        for (int k = 0; k < (TILE*NKV/4)/TB; ++k) {
            int i = tid + k*TB;
            cpa16(dst + (unsigned)i*16u, s + i);
        }
        asm volatile("cp.async.commit_group;");
    }

    const float* Pb = Ps + hg*4*NKV;    // this warp's 4 heads

    for (int t = 0; t < NTILES; ++t) {
        if (t < NTILES-1) asm volatile("cp.async.wait_group 1;");
        else              asm volatile("cp.async.wait_group 0;");
        __syncthreads();

        if (t + 2 < NTILES) {   // stage t+2 into buffer (t+2)%3
            const float4* s = src_base + (size_t)(t+2)*TILE*(NKV/4);
            unsigned dst = kvs_u + (unsigned)(((t+2)%3)*TILE*NKV*4);
            #pragma unroll
            for (int k = 0; k < (TILE*NKV/4)/TB; ++k) {
                int i = tid + k*TB;
                cpa16(dst + (unsigned)i*16u, s + i);
            }
            asm volatile("cp.async.commit_group;");
        }

        const float* kbw = kvs + (t%3)*TILE*NKV + rb*8*NKV;
        #pragma unroll
        for (int g = 0; g < 2; ++g) {
            // load 4 rows into registers (reused by both stages)
            ulonglong2 x[4][4];
            #pragma unroll
            for (int r = 0; r < 4; ++r)
                #pragma unroll
                for (int c = 0; c < 4; ++c)
                    x[r][c] = *(const ulonglong2*)(kbw + (g*4+r)*NKV + c*128 + lane*4);

            // logits: 4 rows x 4 heads; P streamed from smem per chunk
            u64 la[4][4];
            #pragma unroll
            for (int r = 0; r < 4; ++r)
                #pragma unroll
                for (int h = 0; h < 4; ++h) la[r][h] = 0ull;
            #pragma unroll
            for (int c = 0; c < 4; ++c) {
                ulonglong2 p[4];
                #pragma unroll
                for (int h = 0; h < 4; ++h)
                    p[h] = *(const ulonglong2*)(Pb + h*NKV + c*128 + lane*4);
                #pragma unroll
                for (int r = 0; r < 4; ++r)
                    #pragma unroll
                    for (int h = 0; h < 4; ++h) {
                        la[r][h] = ffma2(x[r][c].x, p[h].x, la[r][h]);
                        la[r][h] = ffma2(x[r][c].y, p[h].y, la[r][h]);
                    }
            }
            float v[16];
            #pragma unroll
            for (int r = 0; r < 4; ++r)
                #pragma unroll
                for (int h = 0; h < 4; ++h)
                    v[r*4+h] = lo2(la[r][h]) + hi2(la[r][h]);
            // fold upper half-warp, then reduce-scatter over 16 lanes:
            // lane l (l<16) ends with full logit of index l = r*4+h
            #pragma unroll
            for (int j = 0; j < 16; ++j) v[j] += __shfl_xor_sync(0xffffffffu, v[j], 16);
            #pragma unroll
            for (int half = 8; half >= 1; half >>= 1) {
                const bool up = (lane & half) != 0;
                #pragma unroll
                for (int j = 0; j < half; ++j) {
                    float mine   = up ? v[j+half] : v[j];
                    float theirs = up ? v[j]      : v[j+half];
                    v[j] = mine + __shfl_xor_sync(0xffffffffu, theirs, half);
                }
            }
            float w = __expf(v[0]);        // idx = lane&15: r=(idx>>2), h=idx&3
            if (lane < 16) zacc += w;
            // weighted accumulation; w broadcast fused per (r,h)
            #pragma unroll
            for (int r = 0; r < 4; ++r)
                #pragma unroll
                for (int h = 0; h < 4; ++h) {
                    u64 wd = dup2(__shfl_sync(0xffffffffu, w, r*4 + h));
                    #pragma unroll
                    for (int c = 0; c < 4; ++c) {
                        acc[h][c][0] = ffma2(wd, x[r][c].x, acc[h][c][0]);
                        acc[h][c][1] = ffma2(wd, x[r][c].y, acc[h][c][1]);
                    }
                }
        }
    }

    // ---- epilogue: cross-warp reduce via smem (kvs is free now) ----
    // Each warp owns 2048 floats: [4 heads][512 cols]; 8 warps = 16384
    // floats < 49152-float kv ring: in-bounds.
    __syncthreads();
    {
        float* red = kvs + wid*2048;
        #pragma unroll
        for (int h = 0; h < 4; ++h)
            #pragma unroll
            for (int c = 0; c < 4; ++c)
                *(ulonglong2*)(red + h*NKV + c*128 + lane*4)
                    = make_ulonglong2(acc[h][c][0], acc[h][c][1]);
        if (lane < 16) zs[wid*16 + lane] = zacc;
    }
    __syncthreads();

    const int part = b*NCHUNK + chunk;
    {
        float4* pc = (float4*)(g_partC + (size_t)part*NH*NKV);
        const float4* redv = (const float4*)kvs;   // warp stride 512 float4
        for (int s = tid; s < NH*NKV/4; s += TB) {
            const int h = s >> 7, col4 = s & 127;
            const int hg2 = h >> 2, hl = h & 3;    // warp = rbi*2 + hg2
            float4 a0 = redv[(0*2+hg2)*512 + hl*128 + col4];
            float4 a1 = redv[(1*2+hg2)*512 + hl*128 + col4];
            float4 a2 = redv[(2*2+hg2)*512 + hl*128 + col4];
            float4 a3 = redv[(3*2+hg2)*512 + hl*128 + col4];
            a0.x += a1.x + a2.x + a3.x;
            a0.y += a1.y + a2.y + a3.y;
            a0.z += a1.z + a2.z + a3.z;
            a0.w += a1.w + a2.w + a3.w;
            pc[s] = a0;
        }
    }
    if (tid < NH) {
        const int hg2 = tid >> 2, hl = tid & 3;
        float Z = 0.f;
        #pragma unroll
        for (int rbi = 0; rbi < 4; ++rbi) {
            const int wi = rbi*2 + hg2;
            Z += (zs[wi*16 + hl] + zs[wi*16 + 4 + hl])
               + (zs[wi*16 + 8 + hl] + zs[wi*16 + 12 + hl]);
        }
        g_partZ[part*NH + tid] = Z;
    }
}

// ---------------------------------------------------------------------------
// C (fused): cbar = (sum_chunks partC)/Z in smem, then
// ctx[b, h*64+col] = cbar @ Wv[:, h*64+col] + bv.
// grid (16 b, 8 h) x 256 = 64 cols x 4-way split-K GEMV, MLP8.
// ---------------------------------------------------------------------------
__global__ void __launch_bounds__(256) kernC(
    const float* __restrict__ Wv, const float* __restrict__ bv)
{
    __shared__ float cb_s[NKV];
    __shared__ float red[256];
    const int b = blockIdx.x, h = blockIdx.y, t = threadIdx.x;

    float Z = 0.f;
    #pragma unroll
    for (int i = 0; i < NCHUNK; ++i) Z += g_partZ[(b*NCHUNK + i)*NH + h];
    const float invZ = 1.0f / Z;

    for (int j = t; j < NKV; j += 256) {
        float s = 0.f;
        #pragma unroll
        for (int i = 0; i < NCHUNK; ++i)
            s += g_partC[((size_t)(b*NCHUNK + i)*NH + h)*NKV + j];
        cb_s[j] = s * invZ;
    }
    __syncthreads();

    const int col = h*64 + (t & 63), kp = t >> 6;
    const float* c  = cb_s + kp*128;
    const float* wv = Wv + (size_t)(kp*128)*NE + col;
    float s0=0,s1=0,s2=0,s3=0,s4=0,s5=0,s6=0,s7=0;
    #pragma unroll 4
    for (int j = 0; j < 128; j += 8) {
        s0 = fmaf(c[j+0], wv[(size_t)(j+0)*NE], s0);
        s1 = fmaf(c[j+1], wv[(size_t)(j+1)*NE], s1);
        s2 = fmaf(c[j+2], wv[(size_t)(j+2)*NE], s2);
        s3 = fmaf(c[j+3], wv[(size_t)(j+3)*NE], s3);
        s4 = fmaf(c[j+4], wv[(size_t)(j+4)*NE], s4);
        s5 = fmaf(c[j+5], wv[(size_t)(j+5)*NE], s5);
        s6 = fmaf(c[j+6], wv[(size_t)(j+6)*NE], s6);
        s7 = fmaf(c[j+7], wv[(size_t)(j+7)*NE], s7);
    }
    red[t] = ((s0+s1)+(s2+s3))+((s4+s5)+(s6+s7));
    __syncthreads();
    if (t < 64)
        g_ctx[b*NE + col] = ((red[t]+red[t+64])+(red[t+128]+red[t+192])) + bv[col];
}

// ---------------------------------------------------------------------------
// D: out[b] = ctx[b] @ Wo + bo.  grid (16 b, 8 colblocks) x 256, MLP8.
// ---------------------------------------------------------------------------
__global__ void __launch_bounds__(256) kernD(
    const float* __restrict__ Wo, const float* __restrict__ bo,
    float* __restrict__ out)
{
    __shared__ float cs[NE];
    __shared__ float red[256];
    const int b = blockIdx.x, cb = blockIdx.y, t = threadIdx.x;
    for (int i = t; i < NE; i += 256) cs[i] = g_ctx[b*NE + i];
    __syncthreads();
    const int col = cb*64 + (t & 63), kp = t >> 6;
    const float* c  = cs + kp*128;
    const float* wo = Wo + (size_t)(kp*128)*NE + col;
    float s0=0,s1=0,s2=0,s3=0,s4=0,s5=0,s6=0,s7=0;
    #pragma unroll 4
    for (int j = 0; j < 128; j += 8) {
        s0 = fmaf(c[j+0], wo[(size_t)(j+0)*NE], s0);
        s1 = fmaf(c[j+1], wo[(size_t)(j+1)*NE], s1);
        s2 = fmaf(c[j+2], wo[(size_t)(j+2)*NE], s2);
        s3 = fmaf(c[j+3], wo[(size_t)(j+3)*NE], s3);
        s4 = fmaf(c[j+4], wo[(size_t)(j+4)*NE], s4);
        s5 = fmaf(c[j+5], wo[(size_t)(j+5)*NE], s5);
        s6 = fmaf(c[j+6], wo[(size_t)(j+6)*NE], s6);
        s7 = fmaf(c[j+7], wo[(size_t)(j+7)*NE], s7);
    }
    red[t] = ((s0+s1)+(s2+s3))+((s4+s5)+(s6+s7));
    __syncthreads();
    if (t < 64)
        out[b*NE + col] = ((red[t]+red[t+64])+(red[t+128]+red[t+192])) + bo[col];
}

// ---------------------------------------------------------------------------
extern "C" void kernel_launch(void* const* d_in, const int* in_sizes, int n_in,
                              void* d_out, int out_size)
{
    (void)in_sizes; (void)n_in; (void)out_size;
    const float* query = (const float*)d_in[0];
    const float* kv    = (const float*)d_in[1];
    const float* Wq    = (const float*)d_in[2];
    const float* bq    = (const float*)d_in[3];
    const float* Wk    = (const float*)d_in[4];
    // d_in[5] = bk: softmax-invariant, unused
    const float* Wv    = (const float*)d_in[6];
    const float* bv    = (const float*)d_in[7];
    const float* Wo    = (const float*)d_in[8];
    const float* bo    = (const float*)d_in[9];
    float* out = (float*)d_out;

    const size_t shmB = (size_t)(3*TILE*NKV + NH*NKV + 128) * sizeof(float);
    cudaFuncSetAttribute(kernB, cudaFuncAttributeMaxDynamicSharedMemorySize, (int)shmB);

    kernA1<<<dim3(NB, 8), 256>>>(query, Wq, bq);
    kernA2<<<dim3(8, NH), 256>>>(Wk);
    kernB <<<dim3(NCHUNK, NB), TB, shmB>>>(kv);
    kernC <<<dim3(NB, NH), 256>>>(Wv, bv);
    kernD <<<dim3(NB, 8), 256>>>(Wo, bo, out);
}

// round 13
// speedup vs baseline: 1.3288x; 1.0897x over previous
#include <cuda_runtime.h>
#include <math.h>

// Problem shape (fixed by the reference)
#define NB     16
#define NS     8192
#define NKV    512
#define NE     512
#define NH     8
#define ND     64
#define NCHUNK 8
#define CHUNK  1024
#define TILE   32
#define NTILES (CHUNK/TILE)   // 32
#define TB     256
#define ROWF   516            // padded kv row stride in floats (129 float4)

// Scratch (device globals; allocations forbidden)
__device__ __align__(16) float g_q[NB*NE];
__device__ __align__(16) float g_P[NB*NH*NKV];
__device__ __align__(16) float g_partC[(size_t)NB*NCHUNK*NH*NKV];
__device__ __align__(16) float g_partZ[NB*NCHUNK*NH];
__device__ __align__(16) float g_cbar[NB*NH*NKV];
__device__ __align__(16) float g_ctx[NB*NE];

// ---- packed f32x2 helpers ----
typedef unsigned long long u64;
__device__ __forceinline__ u64 ffma2(u64 a, u64 b, u64 c) {
    u64 d;
    asm("fma.rn.f32x2 %0, %1, %2, %3;" : "=l"(d) : "l"(a), "l"(b), "l"(c));
    return d;
}
__device__ __forceinline__ u64 dup2(float v){
    u64 r; asm("mov.b64 %0, {%1, %1};" : "=l"(r) : "f"(v)); return r;
}
__device__ __forceinline__ void cpa16(unsigned dst, const void* src){
    asm volatile("cp.async.cg.shared.global [%0], [%1], 16;" :: "r"(dst), "l"(src));
}
__device__ __forceinline__ unsigned to_tf32(float v){
    unsigned r; asm("cvt.rna.tf32.f32 %0, %1;" : "=r"(r) : "f"(v)); return r;
}
__device__ __forceinline__ void mma_tf32(
    float& c0, float& c1, float& c2, float& c3,
    unsigned a0, unsigned a1, unsigned a2, unsigned a3,
    unsigned b0, unsigned b1)
{
    asm volatile(
        "mma.sync.aligned.m16n8k8.row.col.f32.tf32.tf32.f32 "
        "{%0,%1,%2,%3}, {%4,%5,%6,%7}, {%8,%9}, {%0,%1,%2,%3};"
        : "+f"(c0), "+f"(c1), "+f"(c2), "+f"(c3)
        : "r"(a0), "r"(a1), "r"(a2), "r"(a3), "r"(b0), "r"(b1));
}

// ---------------------------------------------------------------------------
// A1: q[b,e] = query[b,:] @ Wq[:,e] + bq[e].
// ---------------------------------------------------------------------------
__global__ void __launch_bounds__(256) kernA1(
    const float* __restrict__ query, const float* __restrict__ Wq,
    const float* __restrict__ bq)
{
    __shared__ float qs[NKV];
    __shared__ float red[256];
    const int b = blockIdx.x, eb = blockIdx.y, t = threadIdx.x;
    for (int i = t; i < NKV; i += 256) qs[i] = query[b*NKV + i];
    __syncthreads();
    const int e = eb*64 + (t & 63), kp = t >> 6;
    const float* q  = qs + kp*128;
    const float* wq = Wq + (size_t)(kp*128)*NE + e;
    float s0=0,s1=0,s2=0,s3=0,s4=0,s5=0,s6=0,s7=0;
    #pragma unroll 4
    for (int j = 0; j < 128; j += 8) {
        s0 = fmaf(q[j+0], wq[(size_t)(j+0)*NE], s0);
        s1 = fmaf(q[j+1], wq[(size_t)(j+1)*NE], s1);
        s2 = fmaf(q[j+2], wq[(size_t)(j+2)*NE], s2);
        s3 = fmaf(q[j+3], wq[(size_t)(j+3)*NE], s3);
        s4 = fmaf(q[j+4], wq[(size_t)(j+4)*NE], s4);
        s5 = fmaf(q[j+5], wq[(size_t)(j+5)*NE], s5);
        s6 = fmaf(q[j+6], wq[(size_t)(j+6)*NE], s6);
        s7 = fmaf(q[j+7], wq[(size_t)(j+7)*NE], s7);
    }
    red[t] = ((s0+s1)+(s2+s3))+((s4+s5)+(s6+s7));
    __syncthreads();
    if (t < 64)
        g_q[b*NE + e] = ((red[t]+red[t+64])+(red[t+128]+red[t+192])) + bq[e];
}

// ---------------------------------------------------------------------------
// A2: P[b,h,j] = 0.125 * sum_d g_q[b,h*64+d] * Wk[j,h*64+d]
// ---------------------------------------------------------------------------
__global__ void __launch_bounds__(256) kernA2(const float* __restrict__ Wk)
{
    __shared__ float wks[64*65];
    __shared__ float qhs[16*64];
    const int jb = blockIdx.x, h = blockIdx.y, t = threadIdx.x;

    for (int i = t; i < 64*16; i += 256) {
        int j = i >> 4, d4 = i & 15;
        float4 v = *(const float4*)(Wk + (size_t)(jb*64 + j)*NE + h*ND + d4*4);
        wks[j*65 + d4*4+0] = v.x; wks[j*65 + d4*4+1] = v.y;
        wks[j*65 + d4*4+2] = v.z; wks[j*65 + d4*4+3] = v.w;
    }
    for (int i = t; i < 16*64; i += 256) {
        int bb = i >> 6, d = i & 63;
        qhs[bb*64 + d] = g_q[bb*NE + h*ND + d];
    }
    __syncthreads();

    const int j = t & 63, bg = t >> 6;
    float acc[4] = {0.f,0.f,0.f,0.f};
    const float* wr = wks + j*65;
    #pragma unroll
    for (int d = 0; d < 64; ++d) {
        float wv = wr[d];
        #pragma unroll
        for (int bb = 0; bb < 4; ++bb)
            acc[bb] = fmaf(wv, qhs[(bg*4 + bb)*64 + d], acc[bb]);
    }
    #pragma unroll
    for (int bb = 0; bb < 4; ++bb)
        g_P[((size_t)(bg*4 + bb)*NH + h)*NKV + jb*64 + j] = acc[bb]*0.125f;
}

// ---------------------------------------------------------------------------
// B: fused pass over kv. 256 threads / 8 warps. Per 32-row tile:
//  1) logit GEMM via mma.sync tf32: warp (mb=w&1, ks=w>>1) computes the
//     partial C[16 rows][8 heads] over its 128-wide K slice (16 mmas, P
//     fragments in registers); partials -> smem.
//  2) 256-thread reduce over 4 K slices, one exp per thread, weights stored
//     as (w,w) u64 pairs.
//  3) ffma2 accumulation (R10 mapping): warp rows rb*8..+7, heads hg*4..+3;
//     acc = 4h x 16 cols per lane; w via broadcast LDS.128 (no shuffles).
// No-max softmax (|logit| < ~3). Triple-buffered cp.async; kv row stride 516
// makes the mma A-fragment LDS.32 loads bank-conflict-free.
// ---------------------------------------------------------------------------
__global__ void __launch_bounds__(TB, 1) kernB(const float* __restrict__ kv)
{
    extern __shared__ float sh[];
    float* kvs  = sh;                          // [3][TILE][ROWF]
    u64*   wsm  = (u64*)(sh + 3*TILE*ROWF);    // [2][TILE][NH] (w,w) pairs
    float* part = (float*)(wsm + 2*TILE*NH);   // [8 warps][16 rows][8 heads]
    float* zs   = part + 8*16*8;               // [256]

    const int tid  = threadIdx.x;
    const int wid  = tid >> 5, lane = tid & 31;
    const int chunk = blockIdx.x, b = blockIdx.y;

    // logit-phase mapping
    const int mb = wid & 1, ks = wid >> 1;
    const int gr = lane >> 2, gc = lane & 3;
    // reduction mapping
    const int rrow = tid >> 3, rh = tid & 7;
    const int rmb = rrow >> 4, rr16 = rrow & 15;
    // accum mapping (R10)
    const int rb = wid >> 1, hg = wid & 1;

    // B fragments: P^T slice for this warp's K range, tf32, in registers.
    // b0[kb] = P[head=gr][ks*128 + kb*8 + gc], b1[kb] = same + 4.
    unsigned bq0[16], bq1[16];
    {
        const float* Ph = g_P + ((size_t)b*NH + gr)*NKV + ks*128 + gc;
        #pragma unroll
        for (int kb = 0; kb < 16; ++kb) {
            bq0[kb] = to_tf32(Ph[kb*8]);
            bq1[kb] = to_tf32(Ph[kb*8 + 4]);
        }
    }

    u64 acc[4][4][2];
    #pragma unroll
    for (int h = 0; h < 4; ++h)
        #pragma unroll
        for (int c = 0; c < 4; ++c) { acc[h][c][0] = 0ull; acc[h][c][1] = 0ull; }
    float zacc = 0.f;

    const unsigned kvs_u = (unsigned)__cvta_generic_to_shared(kvs);
    const float4* src_base = (const float4*)kv
        + ((size_t)b*NS + (size_t)chunk*CHUNK)*(NKV/4);

    // prologue: stage tiles 0 and 1 (padded rows: dst float4 index r*129+c4)
    #pragma unroll
    for (int pt = 0; pt < 2; ++pt) {
        const float4* s = src_base + (size_t)pt*TILE*(NKV/4);
        unsigned dst = kvs_u + (unsigned)(pt*TILE*ROWF*4);
        #pragma unroll
        for (int k = 0; k < (TILE*NKV/4)/TB; ++k) {
            int i = tid + k*TB;
            int r = i >> 7, c4 = i & 127;
            cpa16(dst + (unsigned)((r*129 + c4)*16), s + i);
        }
        asm volatile("cp.async.commit_group;");
    }

    for (int t = 0; t < NTILES; ++t) {
        if (t < NTILES-1) asm volatile("cp.async.wait_group 1;");
        else              asm volatile("cp.async.wait_group 0;");
        __syncthreads();                                   // B1

        if (t + 2 < NTILES) {   // stage t+2 into buffer (t+2)%3
            const float4* s = src_base + (size_t)(t+2)*TILE*(NKV/4);
            unsigned dst = kvs_u + (unsigned)(((t+2)%3)*TILE*ROWF*4);
            #pragma unroll
            for (int k = 0; k < (TILE*NKV/4)/TB; ++k) {
                int i = tid + k*TB;
                int r = i >> 7, c4 = i & 127;
                cpa16(dst + (unsigned)((r*129 + c4)*16), s + i);
            }
            asm volatile("cp.async.commit_group;");
        }

        const float* buf = kvs + (t%3)*TILE*ROWF;

        // ---- 1) logit mma: partial C for (mb, ks) ----
        {
            const float* pa = buf + (mb*16 + gr)*ROWF + ks*128 + gc;
            float c0=0.f, c1=0.f, c2=0.f, c3=0.f;
            #pragma unroll
            for (int kb = 0; kb < 16; ++kb) {
                const float* p = pa + kb*8;
                unsigned a0 = __float_as_uint(p[0]);
                unsigned a1 = __float_as_uint(p[8*ROWF]);
                unsigned a2 = __float_as_uint(p[4]);
                unsigned a3 = __float_as_uint(p[8*ROWF + 4]);
                mma_tf32(c0, c1, c2, c3, a0, a1, a2, a3, bq0[kb], bq1[kb]);
            }
            // C mapping: c0=C[gr][2gc], c1=C[gr][2gc+1], c2=C[gr+8][2gc], c3=C[gr+8][2gc+1]
            *(float2*)(part + wid*128 + gr*8 + 2*gc)       = make_float2(c0, c1);
            *(float2*)(part + wid*128 + (gr+8)*8 + 2*gc)   = make_float2(c2, c3);
        }
        __syncthreads();                                   // B2

        // ---- 2) reduce K slices, exp, store (w,w) pairs ----
        {
            const int off = rr16*8 + rh;
            float lg = (part[(rmb+0)*128 + off] + part[(rmb+2)*128 + off])
                     + (part[(rmb+4)*128 + off] + part[(rmb+6)*128 + off]);
            float w = __expf(lg);
            zacc += w;
            wsm[(t & 1)*TILE*NH + rrow*NH + rh] = dup2(w);
        }
        __syncthreads();                                   // B3

        // ---- 3) ffma2 accumulation ----
        {
            const u64* wb = wsm + (t & 1)*TILE*NH + hg*4;
            const float* kr = buf + rb*8*ROWF + lane*4;
            #pragma unroll
            for (int r = 0; r < 8; ++r) {
                ulonglong2 wA = *(const ulonglong2*)(wb + (rb*8 + r)*NH);      // heads 0,1
                ulonglong2 wB = *(const ulonglong2*)(wb + (rb*8 + r)*NH + 2);  // heads 2,3
                #pragma unroll
                for (int c = 0; c < 4; ++c) {
                    ulonglong2 x = *(const ulonglong2*)(kr + r*ROWF + c*128);
                    acc[0][c][0] = ffma2(wA.x, x.x, acc[0][c][0]);
                    acc[0][c][1] = ffma2(wA.x, x.y, acc[0][c][1]);
                    acc[1][c][0] = ffma2(wA.y, x.x, acc[1][c][0]);
                    acc[1][c][1] = ffma2(wA.y, x.y, acc[1][c][1]);
                    acc[2][c][0] = ffma2(wB.x, x.x, acc[2][c][0]);
                    acc[2][c][1] = ffma2(wB.x, x.y, acc[2][c][1]);
                    acc[3][c][0] = ffma2(wB.y, x.x, acc[3][c][0]);
                    acc[3][c][1] = ffma2(wB.y, x.y, acc[3][c][1]);
                }
            }
        }
    }

    // ---- epilogue: cross-warp reduce via smem (kvs is free now) ----
    // Each warp owns 2048 floats: [4 heads][512 cols]; 8 warps = 16384
    // floats << kv ring: in-bounds.
    __syncthreads();
    {
        float* red = kvs + wid*2048;
        #pragma unroll
        for (int h = 0; h < 4; ++h)
            #pragma unroll
            for (int c = 0; c < 4; ++c)
                *(ulonglong2*)(red + h*NKV + c*128 + lane*4)
                    = make_ulonglong2(acc[h][c][0], acc[h][c][1]);
        zs[tid] = zacc;
    }
    __syncthreads();

    const int part_i = b*NCHUNK + chunk;
    {
        float4* pc = (float4*)(g_partC + (size_t)part_i*NH*NKV);
        const float4* redv = (const float4*)kvs;   // warp stride 512 float4
        for (int s = tid; s < NH*NKV/4; s += TB) {
            const int h = s >> 7, col4 = s & 127;
            const int hg2 = h >> 2, hl = h & 3;    // warp = rbi*2 + hg2
            float4 a0 = redv[(0*2+hg2)*512 + hl*128 + col4];
            float4 a1 = redv[(1*2+hg2)*512 + hl*128 + col4];
            float4 a2 = redv[(2*2+hg2)*512 + hl*128 + col4];
            float4 a3 = redv[(3*2+hg2)*512 + hl*128 + col4];
            a0.x += a1.x + a2.x + a3.x;
            a0.y += a1.y + a2.y + a3.y;
            a0.z += a1.z + a2.z + a3.z;
            a0.w += a1.w + a2.w + a3.w;
            pc[s] = a0;
        }
    }
    if (tid < NH) {
        // zacc per thread covers head = tid&7 over its rows; sum all threads
        // with the same head residue.
        float Z = 0.f;
        #pragma unroll
        for (int j = 0; j < 32; ++j) Z += zs[j*8 + tid];
        g_partZ[part_i*NH + tid] = Z;
    }
}

// ---------------------------------------------------------------------------
// C1: cbar[b,h,j] = (sum_i partC[b,i,h,j]) / Z[b,h].  grid 64 x 256
// ---------------------------------------------------------------------------
__global__ void __launch_bounds__(256) kernC1()
{
    const int idx = blockIdx.x*256 + threadIdx.x;      // 16384 float4 slots
    const int b = idx >> 10, rem = idx & 1023, h = rem >> 7, j4 = rem & 127;
    float Z = 0.f;
    #pragma unroll
    for (int i = 0; i < NCHUNK; ++i) Z += g_partZ[(b*NCHUNK + i)*NH + h];
    const float invZ = 1.0f / Z;
    float4 s = make_float4(0.f,0.f,0.f,0.f);
    #pragma unroll
    for (int i = 0; i < NCHUNK; ++i) {
        const float4* p = (const float4*)(g_partC + (((size_t)(b*NCHUNK + i)*NH + h) << 9));
        float4 v = p[j4];
        s.x += v.x; s.y += v.y; s.z += v.z; s.w += v.w;
    }
    s.x *= invZ; s.y *= invZ; s.z *= invZ; s.w *= invZ;
    ((float4*)g_cbar)[((size_t)(b*NH + h) << 7) + j4] = s;
}

// ---------------------------------------------------------------------------
// C2: ctx[b, h*64+col] = cbar[b,h,:] @ Wv[:, h*64+col] + bv.
// ---------------------------------------------------------------------------
__global__ void __launch_bounds__(256) kernC2(
    const float* __restrict__ Wv, const float* __restrict__ bv)
{
    __shared__ float cb_s[NKV];
    __shared__ float red[256];
    const int b = blockIdx.x, h = blockIdx.y, t = threadIdx.x;
    for (int i = t; i < NKV; i += 256) cb_s[i] = g_cbar[(size_t)(b*NH + h)*NKV + i];
    __syncthreads();
    const int col = h*64 + (t & 63), kp = t >> 6;
    const float* c  = cb_s + kp*128;
    const float* wv = Wv + (size_t)(kp*128)*NE + col;
    float s0=0,s1=0,s2=0,s3=0,s4=0,s5=0,s6=0,s7=0;
    #pragma unroll 4
    for (int j = 0; j < 128; j += 8) {
        s0 = fmaf(c[j+0], wv[(size_t)(j+0)*NE], s0);
        s1 = fmaf(c[j+1], wv[(size_t)(j+1)*NE], s1);
        s2 = fmaf(c[j+2], wv[(size_t)(j+2)*NE], s2);
        s3 = fmaf(c[j+3], wv[(size_t)(j+3)*NE], s3);
        s4 = fmaf(c[j+4], wv[(size_t)(j+4)*NE], s4);
        s5 = fmaf(c[j+5], wv[(size_t)(j+5)*NE], s5);
        s6 = fmaf(c[j+6], wv[(size_t)(j+6)*NE], s6);
        s7 = fmaf(c[j+7], wv[(size_t)(j+7)*NE], s7);
    }
    red[t] = ((s0+s1)+(s2+s3))+((s4+s5)+(s6+s7));
    __syncthreads();
    if (t < 64)
        g_ctx[b*NE + col] = ((red[t]+red[t+64])+(red[t+128]+red[t+192])) + bv[col];
}

// ---------------------------------------------------------------------------
// D: out[b] = ctx[b] @ Wo + bo.
// ---------------------------------------------------------------------------
__global__ void __launch_bounds__(256) kernD(
    const float* __restrict__ Wo, const float* __restrict__ bo,
    float* __restrict__ out)
{
    __shared__ float cs[NE];
    __shared__ float red[256];
    const int b = blockIdx.x, cb = blockIdx.y, t = threadIdx.x;
    for (int i = t; i < NE; i += 256) cs[i] = g_ctx[b*NE + i];
    __syncthreads();
    const int col = cb*64 + (t & 63), kp = t >> 6;
    const float* c  = cs + kp*128;
    const float* wo = Wo + (size_t)(kp*128)*NE + col;
    float s0=0,s1=0,s2=0,s3=0,s4=0,s5=0,s6=0,s7=0;
    #pragma unroll 4
    for (int j = 0; j < 128; j += 8) {
        s0 = fmaf(c[j+0], wo[(size_t)(j+0)*NE], s0);
        s1 = fmaf(c[j+1], wo[(size_t)(j+1)*NE], s1);
        s2 = fmaf(c[j+2], wo[(size_t)(j+2)*NE], s2);
        s3 = fmaf(c[j+3], wo[(size_t)(j+3)*NE], s3);
        s4 = fmaf(c[j+4], wo[(size_t)(j+4)*NE], s4);
        s5 = fmaf(c[j+5], wo[(size_t)(j+5)*NE], s5);
        s6 = fmaf(c[j+6], wo[(size_t)(j+6)*NE], s6);
        s7 = fmaf(c[j+7], wo[(size_t)(j+7)*NE], s7);
    }
    red[t] = ((s0+s1)+(s2+s3))+((s4+s5)+(s6+s7));
    __syncthreads();
    if (t < 64)
        out[b*NE + col] = ((red[t]+red[t+64])+(red[t+128]+red[t+192])) + bo[col];
}

// ---------------------------------------------------------------------------
extern "C" void kernel_launch(void* const* d_in, const int* in_sizes, int n_in,
                              void* d_out, int out_size)
{
    (void)in_sizes; (void)n_in; (void)out_size;
    const float* query = (const float*)d_in[0];
    const float* kv    = (const float*)d_in[1];
    const float* Wq    = (const float*)d_in[2];
    const float* bq    = (const float*)d_in[3];
    const float* Wk    = (const float*)d_in[4];
    // d_in[5] = bk: softmax-invariant, unused
    const float* Wv    = (const float*)d_in[6];
    const float* bv    = (const float*)d_in[7];
    const float* Wo    = (const float*)d_in[8];
    const float* bo    = (const float*)d_in[9];
    float* out = (float*)d_out;

    const size_t shmB = (size_t)(3*TILE*ROWF)*sizeof(float)
                      + (size_t)(2*TILE*NH)*sizeof(u64)
                      + (size_t)(8*16*8 + 256)*sizeof(float);
    cudaFuncSetAttribute(kernB, cudaFuncAttributeMaxDynamicSharedMemorySize, (int)shmB);

    kernA1<<<dim3(NB, 8), 256>>>(query, Wq, bq);
    kernA2<<<dim3(8, NH), 256>>>(Wk);
    kernB <<<dim3(NCHUNK, NB), TB, shmB>>>(kv);
    kernC1<<<64, 256>>>();
    kernC2<<<dim3(NB, NH), 256>>>(Wv, bv);
    kernD <<<dim3(NB, 8), 256>>>(Wo, bo, out);
}

// round 14
// speedup vs baseline: 1.4099x; 1.0610x over previous
#include <cuda_runtime.h>
#include <math.h>

// Problem shape (fixed by the reference)
#define NB     16
#define NS     8192
#define NKV    512
#define NE     512
#define NH     8
#define ND     64
#define NCHUNK 8
#define CHUNK  1024
#define TILE   32
#define NTILES (CHUNK/TILE)   // 32
#define TB     256
#define ROWF   516            // padded kv row stride in floats (129 float4)

// Scratch (device globals; allocations forbidden)
__device__ __align__(16) float g_q[NB*NE];
__device__ __align__(16) float g_P[NB*NH*NKV];
__device__ __align__(16) float g_partC[(size_t)NB*NCHUNK*NH*NKV];
__device__ __align__(16) float g_partZ[NB*NCHUNK*NH];
__device__ __align__(16) float g_cbar[NB*NH*NKV];
__device__ __align__(16) float g_ctx[NB*NE];

__device__ __forceinline__ void cpa16(unsigned dst, const void* src){
    asm volatile("cp.async.cg.shared.global [%0], [%1], 16;" :: "r"(dst), "l"(src));
}
__device__ __forceinline__ unsigned to_tf32(float v){
    unsigned r; asm("cvt.rna.tf32.f32 %0, %1;" : "=r"(r) : "f"(v)); return r;
}
__device__ __forceinline__ void mma_tf32(
    float& c0, float& c1, float& c2, float& c3,
    unsigned a0, unsigned a1, unsigned a2, unsigned a3,
    unsigned b0, unsigned b1)
{
    asm volatile(
        "mma.sync.aligned.m16n8k8.row.col.f32.tf32.tf32.f32 "
        "{%0,%1,%2,%3}, {%4,%5,%6,%7}, {%8,%9}, {%0,%1,%2,%3};"
        : "+f"(c0), "+f"(c1), "+f"(c2), "+f"(c3)
        : "r"(a0), "r"(a1), "r"(a2), "r"(a3), "r"(b0), "r"(b1));
}

// ---------------------------------------------------------------------------
// A1: q[b,e] = query[b,:] @ Wq[:,e] + bq[e].
// ---------------------------------------------------------------------------
__global__ void __launch_bounds__(256) kernA1(
    const float* __restrict__ query, const float* __restrict__ Wq,
    const float* __restrict__ bq)
{
    __shared__ float qs[NKV];
    __shared__ float red[256];
    const int b = blockIdx.x, eb = blockIdx.y, t = threadIdx.x;
    for (int i = t; i < NKV; i += 256) qs[i] = query[b*NKV + i];
    __syncthreads();
    const int e = eb*64 + (t & 63), kp = t >> 6;
    const float* q  = qs + kp*128;
    const float* wq = Wq + (size_t)(kp*128)*NE + e;
    float s0=0,s1=0,s2=0,s3=0,s4=0,s5=0,s6=0,s7=0;
    #pragma unroll 4
    for (int j = 0; j < 128; j += 8) {
        s0 = fmaf(q[j+0], wq[(size_t)(j+0)*NE], s0);
        s1 = fmaf(q[j+1], wq[(size_t)(j+1)*NE], s1);
        s2 = fmaf(q[j+2], wq[(size_t)(j+2)*NE], s2);
        s3 = fmaf(q[j+3], wq[(size_t)(j+3)*NE], s3);
        s4 = fmaf(q[j+4], wq[(size_t)(j+4)*NE], s4);
        s5 = fmaf(q[j+5], wq[(size_t)(j+5)*NE], s5);
        s6 = fmaf(q[j+6], wq[(size_t)(j+6)*NE], s6);
        s7 = fmaf(q[j+7], wq[(size_t)(j+7)*NE], s7);
    }
    red[t] = ((s0+s1)+(s2+s3))+((s4+s5)+(s6+s7));
    __syncthreads();
    if (t < 64)
        g_q[b*NE + e] = ((red[t]+red[t+64])+(red[t+128]+red[t+192])) + bq[e];
}

// ---------------------------------------------------------------------------
// A2: P[b,h,j] = 0.125 * sum_d g_q[b,h*64+d] * Wk[j,h*64+d]
// ---------------------------------------------------------------------------
__global__ void __launch_bounds__(256) kernA2(const float* __restrict__ Wk)
{
    __shared__ float wks[64*65];
    __shared__ float qhs[16*64];
    const int jb = blockIdx.x, h = blockIdx.y, t = threadIdx.x;

    for (int i = t; i < 64*16; i += 256) {
        int j = i >> 4, d4 = i & 15;
        float4 v = *(const float4*)(Wk + (size_t)(jb*64 + j)*NE + h*ND + d4*4);
        wks[j*65 + d4*4+0] = v.x; wks[j*65 + d4*4+1] = v.y;
        wks[j*65 + d4*4+2] = v.z; wks[j*65 + d4*4+3] = v.w;
    }
    for (int i = t; i < 16*64; i += 256) {
        int bb = i >> 6, d = i & 63;
        qhs[bb*64 + d] = g_q[bb*NE + h*ND + d];
    }
    __syncthreads();

    const int j = t & 63, bg = t >> 6;
    float acc[4] = {0.f,0.f,0.f,0.f};
    const float* wr = wks + j*65;
    #pragma unroll
    for (int d = 0; d < 64; ++d) {
        float wv = wr[d];
        #pragma unroll
        for (int bb = 0; bb < 4; ++bb)
            acc[bb] = fmaf(wv, qhs[(bg*4 + bb)*64 + d], acc[bb]);
    }
    #pragma unroll
    for (int bb = 0; bb < 4; ++bb)
        g_P[((size_t)(bg*4 + bb)*NH + h)*NKV + jb*64 + j] = acc[bb]*0.125f;
}

// ---------------------------------------------------------------------------
// B: fused pass over kv, BOTH inner products on tensor cores (tf32 mma).
// 256 threads / 8 warps. Per 32-row tile:
//  1) logit GEMM: warp (mb=w&1, ks=w>>1) -> partial C[16 rows][8 heads]
//     over its 128-wide K slice; partials -> smem.
//  2) 256-thread reduce over 4 K slices, one exp per thread; w is rounded
//     to tf32 and that SAME value feeds both Z and the stored weight
//     (keeps weights/normalizer exactly consistent).
//  3) accumulation GEMM: ctx^T[cols x heads] += kv^T[cols x rows] @ w;
//     warp owns 64 cols (4 m16-tiles) x 8 heads x K=32 (4 k8-chunks) =
//     16 mmas; accumulators (16 regs) persist across tiles; each (col,head)
//     owned by ONE warp -> direct STG epilogue, no cross-warp reduce.
// No-max softmax (|logit| < ~3). Triple-buffered cp.async ring; ROWF=516
// makes logit A-frags conflict-free (accum A-frags take 2-way).
// ---------------------------------------------------------------------------
__global__ void __launch_bounds__(TB, 1) kernB(const float* __restrict__ kv)
{
    extern __shared__ float sh[];
    float* kvs  = sh;                          // [3][TILE][ROWF]
    float* wsm  = sh + 3*TILE*ROWF;            // [2][TILE][NH] tf32 weights
    float* part = wsm + 2*TILE*NH;             // [8 warps][16 rows][8 heads]
    float* zs   = part + 8*16*8;               // [256]

    const int tid  = threadIdx.x;
    const int wid  = tid >> 5, lane = tid & 31;
    const int chunk = blockIdx.x, b = blockIdx.y;

    // shared lane decomposition for mma fragments
    const int gr = lane >> 2, gc = lane & 3;
    // logit-phase mapping
    const int mb = wid & 1, ks = wid >> 1;
    // reduction mapping
    const int rrow = tid >> 3, rh = tid & 7;
    const int rmb = rrow >> 4, rr16 = rrow & 15;
    // accum-phase mapping: warp owns cols wid*64..+63

    // Logit B fragments: P^T slice, tf32, in registers.
    unsigned bq0[16], bq1[16];
    {
        const float* Ph = g_P + ((size_t)b*NH + gr)*NKV + ks*128 + gc;
        #pragma unroll
        for (int kb = 0; kb < 16; ++kb) {
            bq0[kb] = to_tf32(Ph[kb*8]);
            bq1[kb] = to_tf32(Ph[kb*8 + 4]);
        }
    }

    // Accum accumulators: D^T[col0+mt*16+{gr,gr+8}][{2gc,2gc+1}]
    float acc[4][4];
    #pragma unroll
    for (int mt = 0; mt < 4; ++mt)
        #pragma unroll
        for (int c = 0; c < 4; ++c) acc[mt][c] = 0.f;
    float zacc = 0.f;

    const unsigned kvs_u = (unsigned)__cvta_generic_to_shared(kvs);
    const float4* src_base = (const float4*)kv
        + ((size_t)b*NS + (size_t)chunk*CHUNK)*(NKV/4);

    // prologue: stage tiles 0 and 1 (padded rows: dst float4 index r*129+c4)
    #pragma unroll
    for (int pt = 0; pt < 2; ++pt) {
        const float4* s = src_base + (size_t)pt*TILE*(NKV/4);
        unsigned dst = kvs_u + (unsigned)(pt*TILE*ROWF*4);
        #pragma unroll
        for (int k = 0; k < (TILE*NKV/4)/TB; ++k) {
            int i = tid + k*TB;
            int r = i >> 7, c4 = i & 127;
            cpa16(dst + (unsigned)((r*129 + c4)*16), s + i);
        }
        asm volatile("cp.async.commit_group;");
    }

    for (int t = 0; t < NTILES; ++t) {
        if (t < NTILES-1) asm volatile("cp.async.wait_group 1;");
        else              asm volatile("cp.async.wait_group 0;");
        __syncthreads();                                   // B1

        if (t + 2 < NTILES) {   // stage t+2 into buffer (t+2)%3
            const float4* s = src_base + (size_t)(t+2)*TILE*(NKV/4);
            unsigned dst = kvs_u + (unsigned)(((t+2)%3)*TILE*ROWF*4);
            #pragma unroll
            for (int k = 0; k < (TILE*NKV/4)/TB; ++k) {
                int i = tid + k*TB;
                int r = i >> 7, c4 = i & 127;
                cpa16(dst + (unsigned)((r*129 + c4)*16), s + i);
            }
            asm volatile("cp.async.commit_group;");
        }

        const float* buf = kvs + (t%3)*TILE*ROWF;

        // ---- 1) logit mma: partial C for (mb, ks) ----
        {
            const float* pa = buf + (mb*16 + gr)*ROWF + ks*128 + gc;
            float c0=0.f, c1=0.f, c2=0.f, c3=0.f;
            #pragma unroll
            for (int kb = 0; kb < 16; ++kb) {
                const float* p = pa + kb*8;
                unsigned a0 = __float_as_uint(p[0]);
                unsigned a1 = __float_as_uint(p[8*ROWF]);
                unsigned a2 = __float_as_uint(p[4]);
                unsigned a3 = __float_as_uint(p[8*ROWF + 4]);
                mma_tf32(c0, c1, c2, c3, a0, a1, a2, a3, bq0[kb], bq1[kb]);
            }
            *(float2*)(part + wid*128 + gr*8 + 2*gc)     = make_float2(c0, c1);
            *(float2*)(part + wid*128 + (gr+8)*8 + 2*gc) = make_float2(c2, c3);
        }
        __syncthreads();                                   // B2

        // ---- 2) reduce K slices, exp, tf32-round, store ----
        {
            const int off = rr16*8 + rh;
            float lg = (part[(rmb+0)*128 + off] + part[(rmb+2)*128 + off])
                     + (part[(rmb+4)*128 + off] + part[(rmb+6)*128 + off]);
            float w = __expf(lg);
            float wf = __uint_as_float(to_tf32(w));   // tf32-rounded weight
            zacc += wf;                               // Z from the SAME value
            wsm[(t & 1)*TILE*NH + rrow*NH + rh] = wf;
        }
        __syncthreads();                                   // B3

        // ---- 3) accumulation mma: ctx^T += kv^T @ w ----
        {
            const float* wt = wsm + (t & 1)*TILE*NH;
            const int col0 = wid*64;
            #pragma unroll
            for (int kc = 0; kc < 4; ++kc) {
                unsigned b0 = __float_as_uint(wt[(kc*8 + gc)*NH + gr]);
                unsigned b1 = __float_as_uint(wt[(kc*8 + gc + 4)*NH + gr]);
                const float* ar0 = buf + (kc*8 + gc)*ROWF + col0 + gr;
                const float* ar1 = buf + (kc*8 + gc + 4)*ROWF + col0 + gr;
                #pragma unroll
                for (int mt = 0; mt < 4; ++mt) {
                    unsigned a0 = __float_as_uint(ar0[mt*16]);
                    unsigned a1 = __float_as_uint(ar0[mt*16 + 8]);
                    unsigned a2 = __float_as_uint(ar1[mt*16]);
                    unsigned a3 = __float_as_uint(ar1[mt*16 + 8]);
                    mma_tf32(acc[mt][0], acc[mt][1], acc[mt][2], acc[mt][3],
                             a0, a1, a2, a3, b0, b1);
                }
            }
        }
    }

    // ---- epilogue: direct STG (each warp owns its cols x all heads) ----
    zs[tid] = zacc;
    __syncthreads();

    const int part_i = b*NCHUNK + chunk;
    {
        float* pc = g_partC + (size_t)part_i*NH*NKV;
        const int col0 = wid*64 + gr;
        #pragma unroll
        for (int mt = 0; mt < 4; ++mt) {
            const int col = col0 + mt*16;
            pc[(size_t)(2*gc  )*NKV + col    ] = acc[mt][0];
            pc[(size_t)(2*gc+1)*NKV + col    ] = acc[mt][1];
            pc[(size_t)(2*gc  )*NKV + col + 8] = acc[mt][2];
            pc[(size_t)(2*gc+1)*NKV + col + 8] = acc[mt][3];
        }
    }
    if (tid < NH) {
        // zacc per thread covers head = tid&7 over its rows
        float Z = 0.f;
        #pragma unroll
        for (int j = 0; j < 32; ++j) Z += zs[j*8 + tid];
        g_partZ[part_i*NH + tid] = Z;
    }
}

// ---------------------------------------------------------------------------
// C1: cbar[b,h,j] = (sum_i partC[b,i,h,j]) / Z[b,h].  grid 64 x 256
// ---------------------------------------------------------------------------
__global__ void __launch_bounds__(256) kernC1()
{
    const int idx = blockIdx.x*256 + threadIdx.x;      // 16384 float4 slots
    const int b = idx >> 10, rem = idx & 1023, h = rem >> 7, j4 = rem & 127;
    float Z = 0.f;
    #pragma unroll
    for (int i = 0; i < NCHUNK; ++i) Z += g_partZ[(b*NCHUNK + i)*NH + h];
    const float invZ = 1.0f / Z;
    float4 s = make_float4(0.f,0.f,0.f,0.f);
    #pragma unroll
    for (int i = 0; i < NCHUNK; ++i) {
        const float4* p = (const float4*)(g_partC + (((size_t)(b*NCHUNK + i)*NH + h) << 9));
        float4 v = p[j4];
        s.x += v.x; s.y += v.y; s.z += v.z; s.w += v.w;
    }
    s.x *= invZ; s.y *= invZ; s.z *= invZ; s.w *= invZ;
    ((float4*)g_cbar)[((size_t)(b*NH + h) << 7) + j4] = s;
}

// ---------------------------------------------------------------------------
// C2: ctx[b, h*64+col] = cbar[b,h,:] @ Wv[:, h*64+col] + bv.
// ---------------------------------------------------------------------------
__global__ void __launch_bounds__(256) kernC2(
    const float* __restrict__ Wv, const float* __restrict__ bv)
{
    __shared__ float cb_s[NKV];
    __shared__ float red[256];
    const int b = blockIdx.x, h = blockIdx.y, t = threadIdx.x;
    for (int i = t; i < NKV; i += 256) cb_s[i] = g_cbar[(size_t)(b*NH + h)*NKV + i];
    __syncthreads();
    const int col = h*64 + (t & 63), kp = t >> 6;
    const float* c  = cb_s + kp*128;
    const float* wv = Wv + (size_t)(kp*128)*NE + col;
    float s0=0,s1=0,s2=0,s3=0,s4=0,s5=0,s6=0,s7=0;
    #pragma unroll 4
    for (int j = 0; j < 128; j += 8) {
        s0 = fmaf(c[j+0], wv[(size_t)(j+0)*NE], s0);
        s1 = fmaf(c[j+1], wv[(size_t)(j+1)*NE], s1);
        s2 = fmaf(c[j+2], wv[(size_t)(j+2)*NE], s2);
        s3 = fmaf(c[j+3], wv[(size_t)(j+3)*NE], s3);
        s4 = fmaf(c[j+4], wv[(size_t)(j+4)*NE], s4);
        s5 = fmaf(c[j+5], wv[(size_t)(j+5)*NE], s5);
        s6 = fmaf(c[j+6], wv[(size_t)(j+6)*NE], s6);
        s7 = fmaf(c[j+7], wv[(size_t)(j+7)*NE], s7);
    }
    red[t] = ((s0+s1)+(s2+s3))+((s4+s5)+(s6+s7));
    __syncthreads();
    if (t < 64)
        g_ctx[b*NE + col] = ((red[t]+red[t+64])+(red[t+128]+red[t+192])) + bv[col];
}

// ---------------------------------------------------------------------------
// D: out[b] = ctx[b] @ Wo + bo.
// ---------------------------------------------------------------------------
__global__ void __launch_bounds__(256) kernD(
    const float* __restrict__ Wo, const float* __restrict__ bo,
    float* __restrict__ out)
{
    __shared__ float cs[NE];
    __shared__ float red[256];
    const int b = blockIdx.x, cb = blockIdx.y, t = threadIdx.x;
    for (int i = t; i < NE; i += 256) cs[i] = g_ctx[b*NE + i];
    __syncthreads();
    const int col = cb*64 + (t & 63), kp = t >> 6;
    const float* c  = cs + kp*128;
    const float* wo = Wo + (size_t)(kp*128)*NE + col;
    float s0=0,s1=0,s2=0,s3=0,s4=0,s5=0,s6=0,s7=0;
    #pragma unroll 4
    for (int j = 0; j < 128; j += 8) {
        s0 = fmaf(c[j+0], wo[(size_t)(j+0)*NE], s0);
        s1 = fmaf(c[j+1], wo[(size_t)(j+1)*NE], s1);
        s2 = fmaf(c[j+2], wo[(size_t)(j+2)*NE], s2);
        s3 = fmaf(c[j+3], wo[(size_t)(j+3)*NE], s3);
        s4 = fmaf(c[j+4], wo[(size_t)(j+4)*NE], s4);
        s5 = fmaf(c[j+5], wo[(size_t)(j+5)*NE], s5);
        s6 = fmaf(c[j+6], wo[(size_t)(j+6)*NE], s6);
        s7 = fmaf(c[j+7], wo[(size_t)(j+7)*NE], s7);
    }
    red[t] = ((s0+s1)+(s2+s3))+((s4+s5)+(s6+s7));
    __syncthreads();
    if (t < 64)
        out[b*NE + col] = ((red[t]+red[t+64])+(red[t+128]+red[t+192])) + bo[col];
}

// ---------------------------------------------------------------------------
extern "C" void kernel_launch(void* const* d_in, const int* in_sizes, int n_in,
                              void* d_out, int out_size)
{
    (void)in_sizes; (void)n_in; (void)out_size;
    const float* query = (const float*)d_in[0];
    const float* kv    = (const float*)d_in[1];
    const float* Wq    = (const float*)d_in[2];
    const float* bq    = (const float*)d_in[3];
    const float* Wk    = (const float*)d_in[4];
    // d_in[5] = bk: softmax-invariant, unused
    const float* Wv    = (const float*)d_in[6];
    const float* bv    = (const float*)d_in[7];
    const float* Wo    = (const float*)d_in[8];
    const float* bo    = (const float*)d_in[9];
    float* out = (float*)d_out;

    const size_t shmB = (size_t)(3*TILE*ROWF + 2*TILE*NH + 8*16*8 + 256)
                        * sizeof(float);
    cudaFuncSetAttribute(kernB, cudaFuncAttributeMaxDynamicSharedMemorySize, (int)shmB);

    kernA1<<<dim3(NB, 8), 256>>>(query, Wq, bq);
    kernA2<<<dim3(8, NH), 256>>>(Wk);
    kernB <<<dim3(NCHUNK, NB), TB, shmB>>>(kv);
    kernC1<<<64, 256>>>();
    kernC2<<<dim3(NB, NH), 256>>>(Wv, bv);
    kernD <<<dim3(NB, 8), 256>>>(Wo, bo, out);
}